// round 1
// baseline (speedup 1.0000x reference)
#include <cuda_runtime.h>

#define NMAX 50000
#define C 96
#define S 16
#define G 6

// Scratch for q/k/v (device globals: allowed, no allocation)
__device__ float g_q[NMAX * C];
__device__ float g_k[NMAX * C];
__device__ float g_v[NMAX * C];

// ---------------------------------------------------------------------------
// Kernel A: q = relu(bn(feat@Wq+bq)), k = relu(bn(feat@Wk+bk)), v = feat@Wv+bv
// Block: 256 threads = (32 x, 8 y). 32 rows per block. Register tile 4 rows x 3 cols.
// ---------------------------------------------------------------------------
__global__ __launch_bounds__(256) void qkv_kernel(
    const float* __restrict__ feat,
    const float* __restrict__ Wq, const float* __restrict__ bq,
    const float* __restrict__ gq, const float* __restrict__ betaq,
    const float* __restrict__ Wk, const float* __restrict__ bk,
    const float* __restrict__ gk, const float* __restrict__ betak,
    const float* __restrict__ Wv, const float* __restrict__ bv,
    int n)
{
    extern __shared__ float sm[];
    float* featT = sm;            // [96][36]  (pitch 36 floats, 16B aligned)
    float* Ws    = sm + C * 36;   // [96][96]
    const int tid = threadIdx.x;
    const int tx = tid & 31, ty = tid >> 5;
    const int base = blockIdx.x * 32;

    for (int i = tid; i < 32 * C; i += 256) {
        int r = i / C, j = i - r * C;
        int gr = base + r;
        featT[j * 36 + r] = (gr < n) ? feat[gr * C + j] : 0.f;
    }

    for (int m = 0; m < 3; m++) {
        const float* W = (m == 0) ? Wq : ((m == 1) ? Wk : Wv);
        __syncthreads();
        for (int i = tid; i < C * C; i += 256) Ws[i] = W[i];
        __syncthreads();

        float acc[4][3];
        #pragma unroll
        for (int a = 0; a < 4; a++)
            #pragma unroll
            for (int b = 0; b < 3; b++) acc[a][b] = 0.f;

        #pragma unroll 4
        for (int j = 0; j < C; j++) {
            float4 f4 = *(const float4*)&featT[j * 36 + 4 * ty];
            float fr[4] = {f4.x, f4.y, f4.z, f4.w};
            float w0 = Ws[j * C + tx];
            float w1 = Ws[j * C + tx + 32];
            float w2 = Ws[j * C + tx + 64];
            #pragma unroll
            for (int a = 0; a < 4; a++) {
                acc[a][0] += fr[a] * w0;
                acc[a][1] += fr[a] * w1;
                acc[a][2] += fr[a] * w2;
            }
        }

        #pragma unroll
        for (int b = 0; b < 3; b++) {
            int c = tx + 32 * b;
            float bb = 0.f, aa = 0.f, be = 0.f;
            if (m == 0)      { bb = bq[c]; aa = gq[c] * rsqrtf(1.00001f); be = betaq[c]; }
            else if (m == 1) { bb = bk[c]; aa = gk[c] * rsqrtf(1.00001f); be = betak[c]; }
            else             { bb = bv[c]; }
            #pragma unroll
            for (int a = 0; a < 4; a++) {
                int row = base + 4 * ty + a;
                if (row < n) {
                    float o = acc[a][b];
                    if (m == 2) {
                        g_v[row * C + c] = o + bb;
                    } else {
                        o = fmaxf((o + bb) * aa + be, 0.f);
                        if (m == 0) g_q[row * C + c] = o;
                        else        g_k[row * C + c] = o;
                    }
                }
            }
        }
    }
}

// ---------------------------------------------------------------------------
// Kernel B: fused per-point attention (persistent blocks, 96 threads).
//   peb = relu(bn(pos@Wp1+bp1))@Wp2+bp2           (hot GEMM, 16x96 per point)
//   rel = k[idx]-q+peb ; vgp = v[idx]+peb
//   w = softmax_s( relu(bn(rel@Ww1+bw1))@Ww2+bw2 ) * mask
//   out[n,g*16+i] = sum_s vgp[s][g*16+i] * w[s][g]
// Weights + folded BN constants loaded to smem ONCE per block.
// ---------------------------------------------------------------------------
// smem layout (float offsets)
#define O_WP2  0        // 9216
#define O_HT   9216     // 96*16 = 1536, hT[j][s]
#define O_REL  10752    // 16*100
#define O_VGP  12352    // 16*100
#define O_QS   13952    // 96
#define O_WP1F 14048    // 96*4 ([j][0..2]=w*ap, [j][3]=bias folded)
#define O_BP2  14432    // 96
#define O_WW1F 14528    // 96*6 (folded with aw)
#define O_BW1F 15104    // 8
#define O_WW2  15112    // 36
#define O_BW2  15148    // 8
#define O_POSS 15156    // 16*4
#define O_MASK 15220    // 16
#define O_WH   15236    // 16*8
#define O_WS   15364    // 16*8
#define O_IDX  15492    // 16 ints
#define SMB_FLOATS 15508

__global__ __launch_bounds__(96) void attn_kernel(
    const float* __restrict__ coord, const int* __restrict__ refidx,
    const float* __restrict__ Wp1, const float* __restrict__ bp1,
    const float* __restrict__ gp,  const float* __restrict__ betap,
    const float* __restrict__ Wp2, const float* __restrict__ bp2,
    const float* __restrict__ Ww1, const float* __restrict__ bw1,
    const float* __restrict__ gw,  const float* __restrict__ betaw,
    const float* __restrict__ Ww2, const float* __restrict__ bw2,
    float* __restrict__ out, int n)
{
    extern __shared__ float sm[];
    float* Wp2s = sm + O_WP2;
    float* hT   = sm + O_HT;
    float* rel  = sm + O_REL;
    float* vgp  = sm + O_VGP;
    float* qs   = sm + O_QS;
    float* Wp1f = sm + O_WP1F;
    float* bp2s = sm + O_BP2;
    float* Ww1f = sm + O_WW1F;
    float* bw1f = sm + O_BW1F;
    float* Ww2s = sm + O_WW2;
    float* bw2s = sm + O_BW2;
    float* poss = sm + O_POSS;
    float* masks= sm + O_MASK;
    float* wh   = sm + O_WH;
    float* wsm  = sm + O_WS;
    int*   idxs = (int*)(sm + O_IDX);

    const int tid = threadIdx.x;

    // ---- one-time per-block weight staging + BN folding ----
    for (int i = tid; i < 9216; i += 96) Wp2s[i] = Wp2[i];
    {
        float ap = gp[tid] * rsqrtf(1.00001f);
        Wp1f[tid * 4 + 0] = Wp1[tid]        * ap;
        Wp1f[tid * 4 + 1] = Wp1[96 + tid]   * ap;
        Wp1f[tid * 4 + 2] = Wp1[192 + tid]  * ap;
        Wp1f[tid * 4 + 3] = bp1[tid] * ap + betap[tid];
        bp2s[tid] = bp2[tid];
    }
    for (int i = tid; i < 576; i += 96) {
        int g = i % 6;
        Ww1f[i] = Ww1[i] * (gw[g] * rsqrtf(1.00001f));
    }
    if (tid < 6) {
        float aw = gw[tid] * rsqrtf(1.00001f);
        bw1f[tid] = bw1[tid] * aw + betaw[tid];
        bw2s[tid] = bw2[tid];
    }
    if (tid < 36) Ww2s[tid] = Ww2[tid];

    const int si = tid / 24, ci = tid % 24;   // GEMM tile roles (4s x 4c)
    const int sL = tid & 15, gL = tid >> 4;   // (s, g) roles

    for (int nn = blockIdx.x; nn < n; nn += gridDim.x) {
        __syncthreads();  // protect smem reuse across loop iterations

        // ---- phase 1a: indices, masks, relative positions, q row ----
        if (tid < 16) {
            int raw = refidx[nn * 16 + tid];
            int vv = raw + 1;
            masks[tid] = (vv > 0) ? 1.f : ((vv < 0) ? -1.f : 0.f);
            int idx = raw; if (idx < 0) idx += n;   // jax-style negative wrap
            idxs[tid] = idx;
            float cx = coord[nn * 3 + 0], cy = coord[nn * 3 + 1], cz = coord[nn * 3 + 2];
            poss[tid * 4 + 0] = coord[idx * 3 + 0] - cx;
            poss[tid * 4 + 1] = coord[idx * 3 + 1] - cy;
            poss[tid * 4 + 2] = coord[idx * 3 + 2] - cz;
        }
        qs[tid] = g_q[nn * C + tid];
        __syncthreads();

        // ---- phase 1b: h[j][s] = relu(folded affine of pos) ----
        {
            float p0 = poss[sL * 4 + 0], p1 = poss[sL * 4 + 1], p2 = poss[sL * 4 + 2];
            #pragma unroll
            for (int m = 0; m < 16; m++) {
                int j = gL + 6 * m;
                float4 wp = *(const float4*)&Wp1f[j * 4];
                float h = wp.w + p0 * wp.x;
                h += p1 * wp.y;
                h += p2 * wp.z;
                hT[j * 16 + sL] = fmaxf(h, 0.f);
            }
        }
        __syncthreads();

        // ---- phase 2: prefetch k/v gathers, then peb GEMM (16x96 = h@Wp2) ----
        float4 kpre[4], vpre[4];
        #pragma unroll
        for (int a = 0; a < 4; a++) {
            int idx = idxs[4 * si + a];
            kpre[a] = *(const float4*)&g_k[idx * C + 4 * ci];
            vpre[a] = *(const float4*)&g_v[idx * C + 4 * ci];
        }

        float acc[4][4];
        {
            float b0 = bp2s[4 * ci + 0], b1 = bp2s[4 * ci + 1];
            float b2 = bp2s[4 * ci + 2], b3 = bp2s[4 * ci + 3];
            #pragma unroll
            for (int a = 0; a < 4; a++) { acc[a][0] = b0; acc[a][1] = b1; acc[a][2] = b2; acc[a][3] = b3; }
        }
        #pragma unroll 8
        for (int j = 0; j < 96; j++) {
            float4 w4 = *(const float4*)&Wp2s[j * 96 + 4 * ci];
            float4 h4 = *(const float4*)&hT[j * 16 + 4 * si];
            float hv[4] = {h4.x, h4.y, h4.z, h4.w};
            float wv[4] = {w4.x, w4.y, w4.z, w4.w};
            #pragma unroll
            for (int a = 0; a < 4; a++)
                #pragma unroll
                for (int b = 0; b < 4; b++)
                    acc[a][b] += hv[a] * wv[b];
        }

        // epilogue: rel = k - q + peb ; vgp = v + peb
        {
            float4 q4 = *(const float4*)&qs[4 * ci];
            float qa[4] = {q4.x, q4.y, q4.z, q4.w};
            #pragma unroll
            for (int a = 0; a < 4; a++) {
                int s = 4 * si + a;
                float kp[4] = {kpre[a].x, kpre[a].y, kpre[a].z, kpre[a].w};
                float vp[4] = {vpre[a].x, vpre[a].y, vpre[a].z, vpre[a].w};
                float4 rr, vv;
                rr.x = kp[0] - qa[0] + acc[a][0];
                rr.y = kp[1] - qa[1] + acc[a][1];
                rr.z = kp[2] - qa[2] + acc[a][2];
                rr.w = kp[3] - qa[3] + acc[a][3];
                vv.x = vp[0] + acc[a][0];
                vv.y = vp[1] + acc[a][1];
                vv.z = vp[2] + acc[a][2];
                vv.w = vp[3] + acc[a][3];
                *(float4*)&rel[s * 100 + 4 * ci] = rr;
                *(float4*)&vgp[s * 100 + 4 * ci] = vv;
            }
        }
        __syncthreads();

        // ---- phase 3: w layer 1 (rel@Ww1, folded BN, relu). thread = (sL, gL) ----
        float l1 = bw1f[gL];
        #pragma unroll 8
        for (int c2 = 0; c2 < 96; c2++)
            l1 += rel[sL * 100 + c2] * Ww1f[c2 * 6 + gL];
        wh[sL * 8 + gL] = fmaxf(l1, 0.f);
        __syncthreads();

        // ---- phase 4: layer 2 + softmax over s (16-wide shfl groups) ----
        float l2 = bw2s[gL];
        #pragma unroll
        for (int g1 = 0; g1 < 6; g1++)
            l2 += wh[sL * 8 + g1] * Ww2s[g1 * 6 + gL];
        float mx = l2;
        #pragma unroll
        for (int off = 8; off >= 1; off >>= 1)
            mx = fmaxf(mx, __shfl_xor_sync(0xffffffffu, mx, off, 16));
        float e = __expf(l2 - mx);
        float ssum = e;
        #pragma unroll
        for (int off = 8; off >= 1; off >>= 1)
            ssum += __shfl_xor_sync(0xffffffffu, ssum, off, 16);
        wsm[sL * 8 + gL] = e / ssum * masks[sL];
        __syncthreads();

        // ---- phase 5: grouped weighted sum over neighbors, coalesced store ----
        float o = 0.f;
        #pragma unroll
        for (int s2 = 0; s2 < 16; s2++)
            o += vgp[s2 * 100 + tid] * wsm[s2 * 8 + gL];
        out[nn * C + tid] = o;
    }
}

extern "C" void kernel_launch(void* const* d_in, const int* in_sizes, int n_in,
                              void* d_out, int out_size) {
    const float* feat  = (const float*)d_in[0];
    const float* coord = (const float*)d_in[1];
    const int*   ref   = (const int*)d_in[2];
    const float* Wq    = (const float*)d_in[3];
    const float* bq    = (const float*)d_in[4];
    const float* gq    = (const float*)d_in[5];
    const float* betaq = (const float*)d_in[6];
    const float* Wk    = (const float*)d_in[7];
    const float* bk    = (const float*)d_in[8];
    const float* gk    = (const float*)d_in[9];
    const float* betak = (const float*)d_in[10];
    const float* Wv    = (const float*)d_in[11];
    const float* bv    = (const float*)d_in[12];
    const float* Wp1   = (const float*)d_in[13];
    const float* bp1   = (const float*)d_in[14];
    const float* gp    = (const float*)d_in[15];
    const float* betap = (const float*)d_in[16];
    const float* Wp2   = (const float*)d_in[17];
    const float* bp2   = (const float*)d_in[18];
    const float* Ww1   = (const float*)d_in[19];
    const float* bw1   = (const float*)d_in[20];
    const float* gw    = (const float*)d_in[21];
    const float* betaw = (const float*)d_in[22];
    const float* Ww2   = (const float*)d_in[23];
    const float* bw2   = (const float*)d_in[24];

    int n = in_sizes[1] / 3;   // coord is [N,3]

    int smA = (C * 36 + C * C) * (int)sizeof(float);
    int smB = SMB_FLOATS * (int)sizeof(float);
    cudaFuncSetAttribute(qkv_kernel,  cudaFuncAttributeMaxDynamicSharedMemorySize, smA);
    cudaFuncSetAttribute(attn_kernel, cudaFuncAttributeMaxDynamicSharedMemorySize, smB);

    int blocksA = (n + 31) / 32;
    qkv_kernel<<<blocksA, 256, smA>>>(feat, Wq, bq, gq, betaq,
                                      Wk, bk, gk, betak, Wv, bv, n);

    int occ = 0;
    cudaOccupancyMaxActiveBlocksPerMultiprocessor(&occ, attn_kernel, 96, smB);
    if (occ < 1) occ = 1;
    int nsm = 0;
    cudaDeviceGetAttribute(&nsm, cudaDevAttrMultiProcessorCount, 0);
    if (nsm <= 0) nsm = 148;
    int blocksB = occ * nsm;
    if (blocksB > n) blocksB = n;

    attn_kernel<<<blocksB, 96, smB>>>(coord, ref,
                                      Wp1, bp1, gp, betap, Wp2, bp2,
                                      Ww1, bw1, gw, betaw, Ww2, bw2,
                                      (float*)d_out, n);
}

// round 2
// speedup vs baseline: 1.9050x; 1.9050x over previous
#include <cuda_runtime.h>

#define NMAX 50000
#define C 96
#define S 16
#define G 6

// device scratch (no allocation allowed)
__device__ float g_v[NMAX * C];
__device__ float g_Q1[NMAX * 8];
__device__ float g_K1[NMAX * 8];
__device__ float g_Ww1f[576];   // [c][g] = Ww1[c,g]*aw[g]
__device__ float g_Ft[600];     // [g][j] pitch 100 : (Wp2 @ Ww1f)^T
__device__ float g_CB[8];       // per-g constant for l1

// ---------------------------------------------------------------------------
// Kernel P: fold BN into Ww1, precompute F = Wp2@Ww1f and l1 constants.
// ---------------------------------------------------------------------------
__global__ void prep_kernel(const float* __restrict__ Ww1, const float* __restrict__ bw1,
                            const float* __restrict__ gw,  const float* __restrict__ betaw,
                            const float* __restrict__ Wp2, const float* __restrict__ bp2)
{
    __shared__ float Ww1fs[576];
    int t = threadIdx.x;  // 96
    #pragma unroll
    for (int g = 0; g < 6; g++) {
        float aw = gw[g] * rsqrtf(1.00001f);
        float w = Ww1[t * 6 + g] * aw;
        Ww1fs[t * 6 + g] = w;
        g_Ww1f[t * 6 + g] = w;
    }
    __syncthreads();
    #pragma unroll
    for (int g = 0; g < 6; g++) {
        float f = 0.f;
        for (int c = 0; c < 96; c++) f += Wp2[t * 96 + c] * Ww1fs[c * 6 + g];
        g_Ft[g * 100 + t] = f;
    }
    if (t < 6) {
        float aw = gw[t] * rsqrtf(1.00001f);
        float cb = bw1[t] * aw + betaw[t];
        for (int c = 0; c < 96; c++) cb += bp2[c] * Ww1fs[c * 6 + t];
        g_CB[t] = cb;
    }
}

// ---------------------------------------------------------------------------
// Kernel A: v = feat@Wv+bv (full rows), Q1 = relu(bn(feat@Wq+bq))@Ww1f,
//           K1 = relu(bn(feat@Wk+bk))@Ww1f.  32 rows / block, 256 threads.
// ---------------------------------------------------------------------------
#define A_FEATT 0          // 96*36
#define A_WS    3456       // 96*96
#define A_W1F   12672      // 576
#define A_ROWS  13248      // 32*100
#define A_FLOATS 16448

__global__ __launch_bounds__(256) void qkv_kernel(
    const float* __restrict__ feat,
    const float* __restrict__ Wq, const float* __restrict__ bq,
    const float* __restrict__ gq, const float* __restrict__ betaq,
    const float* __restrict__ Wk, const float* __restrict__ bk,
    const float* __restrict__ gk, const float* __restrict__ betak,
    const float* __restrict__ Wv, const float* __restrict__ bv,
    int n)
{
    extern __shared__ float sm[];
    float* featT  = sm + A_FEATT;   // [96][36]
    float* Ws     = sm + A_WS;      // [96][96]
    float* Ww1fs  = sm + A_W1F;     // [96][6]
    float* rows   = sm + A_ROWS;    // [32][100]
    const int tid = threadIdx.x;
    const int tx = tid & 31, ty = tid >> 5;
    const int base = blockIdx.x * 32;

    for (int i = tid; i < 32 * C; i += 256) {
        int r = i / C, j = i - r * C;
        int gr = base + r;
        featT[j * 36 + r] = (gr < n) ? feat[gr * C + j] : 0.f;
    }
    for (int i = tid; i < 576; i += 256) Ww1fs[i] = g_Ww1f[i];

    for (int m = 0; m < 3; m++) {
        const float* W = (m == 0) ? Wq : ((m == 1) ? Wk : Wv);
        __syncthreads();
        for (int i = tid; i < C * C; i += 256) Ws[i] = W[i];
        __syncthreads();

        float acc[4][3];
        #pragma unroll
        for (int a = 0; a < 4; a++)
            #pragma unroll
            for (int b = 0; b < 3; b++) acc[a][b] = 0.f;

        #pragma unroll 4
        for (int j = 0; j < C; j++) {
            float4 f4 = *(const float4*)&featT[j * 36 + 4 * ty];
            float fr[4] = {f4.x, f4.y, f4.z, f4.w};
            float w0 = Ws[j * C + tx];
            float w1 = Ws[j * C + tx + 32];
            float w2 = Ws[j * C + tx + 64];
            #pragma unroll
            for (int a = 0; a < 4; a++) {
                acc[a][0] += fr[a] * w0;
                acc[a][1] += fr[a] * w1;
                acc[a][2] += fr[a] * w2;
            }
        }

        if (m == 2) {
            #pragma unroll
            for (int b = 0; b < 3; b++) {
                int c = tx + 32 * b;
                float bb = bv[c];
                #pragma unroll
                for (int a = 0; a < 4; a++) {
                    int row = base + 4 * ty + a;
                    if (row < n) g_v[row * C + c] = acc[a][b] + bb;
                }
            }
        } else {
            #pragma unroll
            for (int b = 0; b < 3; b++) {
                int c = tx + 32 * b;
                float bb, aa, be;
                if (m == 0) { bb = bq[c]; aa = gq[c] * rsqrtf(1.00001f); be = betaq[c]; }
                else        { bb = bk[c]; aa = gk[c] * rsqrtf(1.00001f); be = betak[c]; }
                #pragma unroll
                for (int a = 0; a < 4; a++)
                    rows[(4 * ty + a) * 100 + c] = fmaxf((acc[a][b] + bb) * aa + be, 0.f);
            }
            __syncthreads();
            if (tid < 192) {
                int row = tid / 6, g = tid % 6;
                int grow = base + row;
                if (grow < n) {
                    float s = 0.f;
                    #pragma unroll 8
                    for (int c2 = 0; c2 < 96; c2++)
                        s += rows[row * 100 + c2] * Ww1fs[c2 * 6 + g];
                    if (m == 0) g_Q1[grow * 8 + g] = s;
                    else        g_K1[grow * 8 + g] = s;
                }
            }
        }
    }
}

// ---------------------------------------------------------------------------
// Kernel B: fused attention, 2 points per 192-thread block iteration.
//   h[s,j] = relu(pos_s . Wp1f_j)
//   l1[s,g] = K1[idx_s,g] - Q1[g] + sum_j h[s,j] F[j,g] + CB[g]
//   l2 = relu(l1) @ Ww2 + bw2 ; softmax over s ; * mask
//   A[j,g] = sum_s h[s,j] w[s,g] ; sw[g] = sum_s w[s,g]
//   out[c] = sum_s v[idx_s,c] w[s,g] + sum_j Wp2[j,c] A[j,g] + bp2[c] sw[g]
// ---------------------------------------------------------------------------
// shared-const smem (floats)
#define B_WP2T 0        // [96][100] Wp2 transposed (Wp2T[c][j])
#define B_FT   9600     // [6][100]
#define B_WP1F 10200    // [96][4]
#define B_BP2  10584    // 96
#define B_WW2  10680    // 36 (+pad to 40)
#define B_BW2  10720    // 8
#define B_CB   10728    // 8
#define B_LANE 10736
// per-lane offsets
#define L_HTS  0        // [16][100] h (s-major); later aliased as At[6][100]
#define L_VGS  1600     // [16][100] gathered v
#define L_WHES 3200     // [16][8]  wh, later es
#define L_L2W  3328     // [16][8]  l2, later w (softmaxed)
#define L_POSS 3456     // [16][4]
#define L_MASK 3520     // 16
#define L_SW   3536     // 8
#define L_IDX  3544     // 16 ints
#define L_SIZE 3560
#define B_FLOATS (B_LANE + 2 * L_SIZE)

__global__ __launch_bounds__(192) void attn_kernel(
    const float* __restrict__ coord, const int* __restrict__ refidx,
    const float* __restrict__ Wp1, const float* __restrict__ bp1,
    const float* __restrict__ gp,  const float* __restrict__ betap,
    const float* __restrict__ Wp2, const float* __restrict__ bp2,
    const float* __restrict__ Ww2, const float* __restrict__ bw2,
    float* __restrict__ out, int n)
{
    extern __shared__ float sm[];
    float* Wp2T = sm + B_WP2T;
    float* Fts  = sm + B_FT;
    float* Wp1f = sm + B_WP1F;
    float* bp2s = sm + B_BP2;
    float* Ww2s = sm + B_WW2;
    float* bw2s = sm + B_BW2;
    float* CBs  = sm + B_CB;

    const int tid = threadIdx.x;
    const int pp  = tid / 96;        // point lane 0/1
    const int jr  = tid % 96;        // j-role / c-role index
    const int s2  = jr / 6, g2 = jr % 6;   // (s,g) role
    const int si  = jr / 24, ci = jr % 24; // v-prefetch role

    float* lane = sm + B_LANE + pp * L_SIZE;
    float* hTs  = lane + L_HTS;
    float* At   = lane + L_HTS;     // alias (hTs dead after l1)
    float* vgs  = lane + L_VGS;
    float* whes = lane + L_WHES;
    float* l2w  = lane + L_L2W;
    float* poss = lane + L_POSS;
    float* masks= lane + L_MASK;
    float* swv  = lane + L_SW;
    int*   idxs = (int*)(lane + L_IDX);

    // ---- one-time staging ----
    for (int i = tid; i < 9216; i += 192) {
        int j = i / 96, c = i % 96;
        Wp2T[c * 100 + j] = Wp2[i];
    }
    for (int i = tid; i < 600; i += 192) Fts[i] = g_Ft[i];
    if (tid < 96) {
        float ap = gp[tid] * rsqrtf(1.00001f);
        Wp1f[tid * 4 + 0] = Wp1[tid]       * ap;
        Wp1f[tid * 4 + 1] = Wp1[96 + tid]  * ap;
        Wp1f[tid * 4 + 2] = Wp1[192 + tid] * ap;
        Wp1f[tid * 4 + 3] = bp1[tid] * ap + betap[tid];
        bp2s[tid] = bp2[tid];
    }
    if (tid < 36) Ww2s[tid] = Ww2[tid];
    if (tid < 6)  { bw2s[tid] = bw2[tid]; CBs[tid] = g_CB[tid]; }

    for (int it = blockIdx.x; it * 2 < n; it += gridDim.x) {
        int nn = it * 2 + pp;
        bool active = (nn < n);
        __syncthreads();  // guard smem reuse across iterations + init on first

        // ---- phase 1: idx / mask / relative positions ----
        if (active && jr < 16) {
            int raw = refidx[nn * 16 + jr];
            int vv = raw + 1;
            masks[jr] = (vv > 0) ? 1.f : ((vv < 0) ? -1.f : 0.f);
            int idx = raw; if (idx < 0) idx += n;
            idxs[jr] = idx;
            float cx = coord[nn * 3 + 0], cy = coord[nn * 3 + 1], cz = coord[nn * 3 + 2];
            poss[jr * 4 + 0] = coord[idx * 3 + 0] - cx;
            poss[jr * 4 + 1] = coord[idx * 3 + 1] - cy;
            poss[jr * 4 + 2] = coord[idx * 3 + 2] - cz;
        }
        __syncthreads();

        // ---- phase 2: h compute + gather prefetch ----
        float h[16];
        float4 vpre[4];
        float k1 = 0.f, q1 = 0.f;
        if (active) {
            // prefetch gathers first (hide L2 latency under h FMAs)
            #pragma unroll
            for (int a = 0; a < 4; a++)
                vpre[a] = *(const float4*)&g_v[idxs[4 * si + a] * C + 4 * ci];
            k1 = g_K1[idxs[s2] * 8 + g2];
            q1 = g_Q1[nn * 8 + g2];

            float4 wp = *(const float4*)&Wp1f[jr * 4];
            #pragma unroll
            for (int s = 0; s < 16; s++) {
                float4 p = *(const float4*)&poss[s * 4];
                float hv = fmaxf(wp.w + p.x * wp.x + p.y * wp.y + p.z * wp.z, 0.f);
                h[s] = hv;
                hTs[s * 100 + jr] = hv;
            }
        }
        __syncthreads();

        // ---- phase 3: l1[s,g], stash v into smem ----
        if (active) {
            #pragma unroll
            for (int a = 0; a < 4; a++)
                *(float4*)&vgs[(4 * si + a) * 100 + 4 * ci] = vpre[a];

            float acc = CBs[g2] + k1 - q1;
            #pragma unroll
            for (int j = 0; j < 96; j += 4) {
                float4 hh = *(const float4*)&hTs[s2 * 100 + j];
                float4 ff = *(const float4*)&Fts[g2 * 100 + j];
                acc += hh.x * ff.x + hh.y * ff.y + hh.z * ff.z + hh.w * ff.w;
            }
            whes[s2 * 8 + g2] = fmaxf(acc, 0.f);
        }
        __syncthreads();

        // ---- phase 4: l2 ----
        float l2 = 0.f;
        if (active) {
            l2 = bw2s[g2];
            #pragma unroll
            for (int gg = 0; gg < 6; gg++)
                l2 += whes[s2 * 8 + gg] * Ww2s[gg * 6 + g2];
            l2w[s2 * 8 + g2] = l2;
        }
        __syncthreads();

        // ---- phase 5: softmax max + exp ----
        float e = 0.f;
        if (active) {
            float mx = -1e30f;
            #pragma unroll
            for (int sp = 0; sp < 16; sp++)
                mx = fmaxf(mx, l2w[sp * 8 + g2]);
            e = __expf(l2 - mx);
            whes[s2 * 8 + g2] = e;  // es
        }
        __syncthreads();

        // ---- phase 6: softmax sum, masked weights, sw ----
        if (active) {
            float ssum = 0.f, msum = 0.f;
            #pragma unroll
            for (int sp = 0; sp < 16; sp++) {
                float ee = whes[sp * 8 + g2];
                ssum += ee;
                msum += ee * masks[sp];
            }
            float w = e * masks[s2] / ssum;
            l2w[s2 * 8 + g2] = w;       // wsm
            if (s2 == 0) swv[g2] = msum / ssum;
        }
        __syncthreads();

        // ---- phase 7: A[j,g] = sum_s h[s,j] w[s,g] ----
        if (active) {
            float A0 = 0.f, A1 = 0.f, A2 = 0.f, A3 = 0.f, A4 = 0.f, A5 = 0.f;
            #pragma unroll
            for (int s = 0; s < 16; s++) {
                float hv = h[s];
                float4 wa = *(const float4*)&l2w[s * 8];
                float4 wb = *(const float4*)&l2w[s * 8 + 4];
                A0 += hv * wa.x; A1 += hv * wa.y; A2 += hv * wa.z;
                A3 += hv * wa.w; A4 += hv * wb.x; A5 += hv * wb.y;
            }
            At[0 * 100 + jr] = A0; At[1 * 100 + jr] = A1; At[2 * 100 + jr] = A2;
            At[3 * 100 + jr] = A3; At[4 * 100 + jr] = A4; At[5 * 100 + jr] = A5;
        }
        __syncthreads();

        // ---- phase 8: output ----
        if (active) {
            int c = jr, g = c >> 4;
            float o = bp2s[c] * swv[g];
            #pragma unroll
            for (int s = 0; s < 16; s++)
                o += vgs[s * 100 + c] * l2w[s * 8 + g];
            #pragma unroll
            for (int j = 0; j < 96; j += 4) {
                float4 w2 = *(const float4*)&Wp2T[c * 100 + j];
                float4 a4 = *(const float4*)&At[g * 100 + j];
                o += w2.x * a4.x + w2.y * a4.y + w2.z * a4.z + w2.w * a4.w;
            }
            out[nn * C + c] = o;
        }
    }
}

extern "C" void kernel_launch(void* const* d_in, const int* in_sizes, int n_in,
                              void* d_out, int out_size) {
    const float* feat  = (const float*)d_in[0];
    const float* coord = (const float*)d_in[1];
    const int*   ref   = (const int*)d_in[2];
    const float* Wq    = (const float*)d_in[3];
    const float* bq    = (const float*)d_in[4];
    const float* gq    = (const float*)d_in[5];
    const float* betaq = (const float*)d_in[6];
    const float* Wk    = (const float*)d_in[7];
    const float* bk    = (const float*)d_in[8];
    const float* gk    = (const float*)d_in[9];
    const float* betak = (const float*)d_in[10];
    const float* Wv    = (const float*)d_in[11];
    const float* bv    = (const float*)d_in[12];
    const float* Wp1   = (const float*)d_in[13];
    const float* bp1   = (const float*)d_in[14];
    const float* gp    = (const float*)d_in[15];
    const float* betap = (const float*)d_in[16];
    const float* Wp2   = (const float*)d_in[17];
    const float* bp2   = (const float*)d_in[18];
    const float* Ww1   = (const float*)d_in[19];
    const float* bw1   = (const float*)d_in[20];
    const float* gw    = (const float*)d_in[21];
    const float* betaw = (const float*)d_in[22];
    const float* Ww2   = (const float*)d_in[23];
    const float* bw2   = (const float*)d_in[24];

    int n = in_sizes[1] / 3;

    int smA = A_FLOATS * (int)sizeof(float);
    int smB = B_FLOATS * (int)sizeof(float);
    cudaFuncSetAttribute(qkv_kernel,  cudaFuncAttributeMaxDynamicSharedMemorySize, smA);
    cudaFuncSetAttribute(attn_kernel, cudaFuncAttributeMaxDynamicSharedMemorySize, smB);

    prep_kernel<<<1, 96>>>(Ww1, bw1, gw, betaw, Wp2, bp2);

    int blocksA = (n + 31) / 32;
    qkv_kernel<<<blocksA, 256, smA>>>(feat, Wq, bq, gq, betaq,
                                      Wk, bk, gk, betak, Wv, bv, n);

    int occ = 0;
    cudaOccupancyMaxActiveBlocksPerMultiprocessor(&occ, attn_kernel, 192, smB);
    if (occ < 1) occ = 1;
    int nsm = 0;
    cudaDeviceGetAttribute(&nsm, cudaDevAttrMultiProcessorCount, 0);
    if (nsm <= 0) nsm = 148;
    int blocksB = occ * nsm;
    int pairs = (n + 1) / 2;
    if (blocksB > pairs) blocksB = pairs;

    attn_kernel<<<blocksB, 192, smB>>>(coord, ref,
                                       Wp1, bp1, gp, betap, Wp2, bp2,
                                       Ww2, bw2, (float*)d_out, n);
}

// round 3
// speedup vs baseline: 2.2315x; 1.1714x over previous
#include <cuda_runtime.h>

#define NMAX 50000
#define C 96

__device__ float g_v[NMAX * C];
__device__ float g_Q1[NMAX * 8];
__device__ float g_K1[NMAX * 8];

// ---------------------------------------------------------------------------
// Kernel A: v = feat@Wv+bv, Q1 = relu(bn(feat@Wq+bq))@Ww1f, K1 likewise.
// 64 rows/block, 192 threads, 8x4 register tile, all-float4 smem loads.
// ---------------------------------------------------------------------------
#define A_FEATT 0            // 96*68
#define A_WS    6528         // 96*96
#define A_W1F   15744        // 576
#define A_ROWS  16320        // 64*100
#define A_FLOATS 22720

__global__ __launch_bounds__(192) void qkv_kernel(
    const float* __restrict__ feat,
    const float* __restrict__ Wq, const float* __restrict__ bq,
    const float* __restrict__ gq, const float* __restrict__ betaq,
    const float* __restrict__ Wk, const float* __restrict__ bk,
    const float* __restrict__ gk, const float* __restrict__ betak,
    const float* __restrict__ Wv, const float* __restrict__ bv,
    const float* __restrict__ Ww1, const float* __restrict__ gw,
    int n)
{
    extern __shared__ float sm[];
    float* featT = sm + A_FEATT;   // [96][68]
    float* Ws    = sm + A_WS;      // [96][96]
    float* Ww1fs = sm + A_W1F;     // [96][6]
    float* rows  = sm + A_ROWS;    // [64][100]
    const int tid = threadIdx.x;
    const int tx = tid % 24, ty = tid / 24;   // 24 col-groups x 8 row-groups
    const int base = blockIdx.x * 64;

    for (int i = tid; i < 64 * 96; i += 192) {
        int r = i / 96, j = i % 96;
        featT[j * 68 + r] = (base + r < n) ? feat[(base + r) * 96 + j] : 0.f;
    }
    for (int i = tid; i < 576; i += 192) {
        int g = i % 6;
        Ww1fs[i] = Ww1[i] * (gw[g] * rsqrtf(1.00001f));
    }

    for (int m = 0; m < 3; m++) {
        const float* W = (m == 0) ? Wq : ((m == 1) ? Wk : Wv);
        __syncthreads();
        for (int i = tid; i < 96 * 96; i += 192) Ws[i] = W[i];
        __syncthreads();

        float acc[8][4];
        #pragma unroll
        for (int a = 0; a < 8; a++)
            #pragma unroll
            for (int b = 0; b < 4; b++) acc[a][b] = 0.f;

        #pragma unroll 4
        for (int j = 0; j < 96; j++) {
            float4 f0 = *(const float4*)&featT[j * 68 + 8 * ty];
            float4 f1 = *(const float4*)&featT[j * 68 + 8 * ty + 4];
            float4 w4 = *(const float4*)&Ws[j * 96 + 4 * tx];
            float fr[8] = {f0.x, f0.y, f0.z, f0.w, f1.x, f1.y, f1.z, f1.w};
            float wv[4] = {w4.x, w4.y, w4.z, w4.w};
            #pragma unroll
            for (int a = 0; a < 8; a++)
                #pragma unroll
                for (int b = 0; b < 4; b++)
                    acc[a][b] += fr[a] * wv[b];
        }

        if (m == 2) {
            int c = 4 * tx;
            float4 bb = *(const float4*)&bv[c];
            #pragma unroll
            for (int a = 0; a < 8; a++) {
                int row = base + 8 * ty + a;
                if (row < n) {
                    float4 o = {acc[a][0] + bb.x, acc[a][1] + bb.y,
                                acc[a][2] + bb.z, acc[a][3] + bb.w};
                    *(float4*)&g_v[row * 96 + c] = o;
                }
            }
        } else {
            int c = 4 * tx;
            const float* bsrc = (m == 0) ? bq : bk;
            const float* gsrc = (m == 0) ? gq : gk;
            const float* besrc = (m == 0) ? betaq : betak;
            float4 bb = *(const float4*)&bsrc[c];
            float4 gg = *(const float4*)&gsrc[c];
            float4 be = *(const float4*)&besrc[c];
            float rs = rsqrtf(1.00001f);
            float aa[4] = {gg.x * rs, gg.y * rs, gg.z * rs, gg.w * rs};
            float bba[4] = {bb.x, bb.y, bb.z, bb.w};
            float bea[4] = {be.x, be.y, be.z, be.w};
            #pragma unroll
            for (int a = 0; a < 8; a++) {
                float4 o;
                o.x = fmaxf((acc[a][0] + bba[0]) * aa[0] + bea[0], 0.f);
                o.y = fmaxf((acc[a][1] + bba[1]) * aa[1] + bea[1], 0.f);
                o.z = fmaxf((acc[a][2] + bba[2]) * aa[2] + bea[2], 0.f);
                o.w = fmaxf((acc[a][3] + bba[3]) * aa[3] + bea[3], 0.f);
                *(float4*)&rows[(8 * ty + a) * 100 + c] = o;
            }
            __syncthreads();
            float* dst = (m == 0) ? g_Q1 : g_K1;
            for (int i = tid; i < 384; i += 192) {
                int r = i / 6, g = i % 6;
                if (base + r < n) {
                    float s = 0.f;
                    #pragma unroll 8
                    for (int c2 = 0; c2 < 96; c2++)
                        s += rows[r * 100 + c2] * Ww1fs[c2 * 6 + g];
                    dst[(base + r) * 8 + g] = s;
                }
            }
        }
    }
}

// ---------------------------------------------------------------------------
// Kernel B: fused attention. 384 threads = 4 point-lanes x 96.
// ---------------------------------------------------------------------------
// shared smem offsets (floats)
#define SH_WP2T 0        // [96][100]
#define SH_FT   9600     // [6][100]
#define SH_WP1F 10200    // [96][4]
#define SH_BP2  10584    // 96
#define SH_WW2  10680    // 40
#define SH_BW2  10720    // 8
#define SH_CB   10728    // 8
#define SH_W1F  10736    // 576
#define SH_PART 11312    // [16][96]
#define SH_LANE 12848
// per-lane (floats)
#define L_HT   0         // [16][100] h; aliased as At[6][100] later
#define L_WH   1600      // [16][8]
#define L_LW   1728      // [16][8]
#define L_POS  1856      // [16][4]
#define L_MSK  1920      // 16
#define L_SW   1936      // 8
#define L_IDX  1944      // 2 parities x 16 ints
#define LZ     1984
#define B_FLOATS (SH_LANE + 4 * LZ)

__global__ __launch_bounds__(384, 2) void attn_kernel(
    const float* __restrict__ coord, const int* __restrict__ refidx,
    const float* __restrict__ Wp1, const float* __restrict__ bp1,
    const float* __restrict__ gp,  const float* __restrict__ betap,
    const float* __restrict__ Wp2, const float* __restrict__ bp2,
    const float* __restrict__ Ww1, const float* __restrict__ bw1,
    const float* __restrict__ gw,  const float* __restrict__ betaw,
    const float* __restrict__ Ww2, const float* __restrict__ bw2,
    float* __restrict__ out, int n)
{
    extern __shared__ float sm[];
    float* Wp2T  = sm + SH_WP2T;
    float* Fts   = sm + SH_FT;
    float* Wp1f  = sm + SH_WP1F;
    float* bp2s  = sm + SH_BP2;
    float* Ww2s  = sm + SH_WW2;
    float* bw2s  = sm + SH_BW2;
    float* CBs   = sm + SH_CB;
    float* Ww1fs = sm + SH_W1F;
    float* part  = sm + SH_PART;

    const int tid = threadIdx.x;
    const int pp  = tid / 96;      // lane (point slot) 0..3
    const int jr  = tid % 96;      // j / c role
    const int sL  = jr & 15, gL = jr >> 4;   // (s,g) role, 16-lane shfl groups

    float* lane  = sm + SH_LANE + pp * LZ;
    float* hT    = lane + L_HT;
    float* At    = lane + L_HT;    // alias
    float* whes  = lane + L_WH;
    float* l2w   = lane + L_LW;
    float* poss  = lane + L_POS;
    float* masks = lane + L_MSK;
    float* swv   = lane + L_SW;
    int*   idxp  = (int*)(lane + L_IDX);

    // ---- one-time staging ----
    for (int i = tid; i < 9216; i += 384)
        Wp2T[(i % 96) * 100 + i / 96] = Wp2[i];
    if (tid < 96) {
        float ap = gp[tid] * rsqrtf(1.00001f);
        Wp1f[tid * 4 + 0] = Wp1[tid]       * ap;
        Wp1f[tid * 4 + 1] = Wp1[96 + tid]  * ap;
        Wp1f[tid * 4 + 2] = Wp1[192 + tid] * ap;
        Wp1f[tid * 4 + 3] = bp1[tid] * ap + betap[tid];
        bp2s[tid] = bp2[tid];
    }
    if (tid < 36) Ww2s[tid] = Ww2[tid];
    if (tid < 6)  bw2s[tid] = bw2[tid];
    for (int i = tid; i < 576; i += 384) {
        int g = i % 6;
        Ww1fs[i] = Ww1[i] * (gw[g] * rsqrtf(1.00001f));
    }
    __syncthreads();
    for (int i = tid; i < 576; i += 384) {
        int j = i / 6, g = i % 6;
        float f = 0.f;
        #pragma unroll 8
        for (int c = 0; c < 96; c++) f += Wp2T[c * 100 + j] * Ww1fs[c * 6 + g];
        Fts[g * 100 + j] = f;
    }
    if (tid < 6) {
        float aw = gw[tid] * rsqrtf(1.00001f);
        float cb = bw1[tid] * aw + betaw[tid];
        for (int c = 0; c < 96; c++) cb += bp2s[c] * Ww1fs[c * 6 + tid];
        CBs[tid] = cb;
    }
    __syncthreads();

    int par = 0;
    for (int it = blockIdx.x; it * 4 < n; it += gridDim.x) {
        int nn = it * 4 + pp;
        bool act = (nn < n);

        // ---- ph1: idx / mask / relative positions ----
        if (act && jr < 16) {
            int raw = refidx[nn * 16 + jr];
            int vv = raw + 1;
            masks[jr] = (vv > 0) ? 1.f : ((vv < 0) ? -1.f : 0.f);
            int idx = (raw < 0) ? raw + n : raw;
            idxp[par * 16 + jr] = idx;
            float cx = coord[nn * 3 + 0], cy = coord[nn * 3 + 1], cz = coord[nn * 3 + 2];
            poss[jr * 4 + 0] = coord[idx * 3 + 0] - cx;
            poss[jr * 4 + 1] = coord[idx * 3 + 1] - cy;
            poss[jr * 4 + 2] = coord[idx * 3 + 2] - cz;
        }
        __syncthreads();

        // ---- ph2: h[s] per thread-j ----
        float h[16];
        if (act) {
            float4 wp = *(const float4*)&Wp1f[jr * 4];
            #pragma unroll
            for (int s = 0; s < 16; s++) {
                float4 p = *(const float4*)&poss[s * 4];
                float hv = fmaxf(wp.w + p.x * wp.x + p.y * wp.y + p.z * wp.z, 0.f);
                h[s] = hv;
                hT[s * 100 + jr] = hv;
            }
        }
        __syncthreads();

        // ---- ph3: wh[s,g] = relu(l1) ----
        if (act) {
            int idx = idxp[par * 16 + sL];
            float acc = CBs[gL] + g_K1[idx * 8 + gL] - g_Q1[nn * 8 + gL];
            #pragma unroll
            for (int j = 0; j < 96; j += 4) {
                float4 hh = *(const float4*)&hT[sL * 100 + j];
                float4 ff = *(const float4*)&Fts[gL * 100 + j];
                acc += hh.x * ff.x + hh.y * ff.y + hh.z * ff.z + hh.w * ff.w;
            }
            whes[sL * 8 + gL] = fmaxf(acc, 0.f);
        }
        __syncthreads();

        // ---- ph456: l2, softmax over s via 16-lane shfl, masked weights ----
        if (act) {
            float l2 = bw2s[gL];
            #pragma unroll
            for (int gg = 0; gg < 6; gg++)
                l2 += whes[sL * 8 + gg] * Ww2s[gg * 6 + gL];
            float mx = l2;
            #pragma unroll
            for (int off = 8; off >= 1; off >>= 1)
                mx = fmaxf(mx, __shfl_xor_sync(0xffffffffu, mx, off, 16));
            float e  = __expf(l2 - mx);
            float em = e * masks[sL];
            float ss = e, ms = em;
            #pragma unroll
            for (int off = 8; off >= 1; off >>= 1) {
                ss += __shfl_xor_sync(0xffffffffu, ss, off, 16);
                ms += __shfl_xor_sync(0xffffffffu, ms, off, 16);
            }
            l2w[sL * 8 + gL] = em / ss;
            if (sL == 0) swv[gL] = ms / ss;
        }
        __syncthreads();

        // ---- ph7: A[j,g] = sum_s h[s,j] w[s,g] (thread-j role) ----
        if (act) {
            float A0 = 0.f, A1 = 0.f, A2 = 0.f, A3 = 0.f, A4 = 0.f, A5 = 0.f;
            #pragma unroll
            for (int s = 0; s < 16; s++) {
                float hv = h[s];
                float4 wa = *(const float4*)&l2w[s * 8];
                float4 wb = *(const float4*)&l2w[s * 8 + 4];
                A0 += hv * wa.x; A1 += hv * wa.y; A2 += hv * wa.z;
                A3 += hv * wa.w; A4 += hv * wb.x; A5 += hv * wb.y;
            }
            At[0 * 100 + jr] = A0; At[1 * 100 + jr] = A1; At[2 * 100 + jr] = A2;
            At[3 * 100 + jr] = A3; At[4 * 100 + jr] = A4; At[5 * 100 + jr] = A5;
        }
        __syncthreads();

        // ---- ph8a: cooperative Wp2^T @ A — each thread handles a j-quarter
        //      for ALL 4 points (reads Wp2 column once per 4 points) ----
        {
            int c = jr, qq = pp, g = jr >> 4;
            int j0 = qq * 24;
            float pt[4] = {0.f, 0.f, 0.f, 0.f};
            #pragma unroll
            for (int j = 0; j < 24; j += 4) {
                float4 wv = *(const float4*)&Wp2T[c * 100 + j0 + j];
                #pragma unroll
                for (int p = 0; p < 4; p++) {
                    const float* Ap = sm + SH_LANE + p * LZ + L_HT;
                    float4 av = *(const float4*)&Ap[g * 100 + j0 + j];
                    pt[p] += wv.x * av.x + wv.y * av.y + wv.z * av.z + wv.w * av.w;
                }
            }
            #pragma unroll
            for (int p = 0; p < 4; p++)
                part[(qq * 4 + p) * 96 + c] = pt[p];
        }
        __syncthreads();

        // ---- ph8b: combine quarters + v-gather term, store out ----
        if (act) {
            int c = jr, g = jr >> 4;
            const int* idq = (const int*)(lane + L_IDX) + par * 16;
            float o = bp2s[c] * swv[g];
            o += part[(0 * 4 + pp) * 96 + c] + part[(1 * 4 + pp) * 96 + c]
               + part[(2 * 4 + pp) * 96 + c] + part[(3 * 4 + pp) * 96 + c];
            float vv[16];
            #pragma unroll
            for (int s = 0; s < 16; s++)
                vv[s] = g_v[idq[s] * 96 + c];
            #pragma unroll
            for (int s = 0; s < 16; s++)
                o += vv[s] * l2w[s * 8 + g];
            out[nn * 96 + c] = o;
        }
        par ^= 1;
    }
}

extern "C" void kernel_launch(void* const* d_in, const int* in_sizes, int n_in,
                              void* d_out, int out_size) {
    const float* feat  = (const float*)d_in[0];
    const float* coord = (const float*)d_in[1];
    const int*   ref   = (const int*)d_in[2];
    const float* Wq    = (const float*)d_in[3];
    const float* bq    = (const float*)d_in[4];
    const float* gq    = (const float*)d_in[5];
    const float* betaq = (const float*)d_in[6];
    const float* Wk    = (const float*)d_in[7];
    const float* bk    = (const float*)d_in[8];
    const float* gk    = (const float*)d_in[9];
    const float* betak = (const float*)d_in[10];
    const float* Wv    = (const float*)d_in[11];
    const float* bv    = (const float*)d_in[12];
    const float* Wp1   = (const float*)d_in[13];
    const float* bp1   = (const float*)d_in[14];
    const float* gp    = (const float*)d_in[15];
    const float* betap = (const float*)d_in[16];
    const float* Wp2   = (const float*)d_in[17];
    const float* bp2   = (const float*)d_in[18];
    const float* Ww1   = (const float*)d_in[19];
    const float* bw1   = (const float*)d_in[20];
    const float* gw    = (const float*)d_in[21];
    const float* betaw = (const float*)d_in[22];
    const float* Ww2   = (const float*)d_in[23];
    const float* bw2   = (const float*)d_in[24];

    int n = in_sizes[1] / 3;

    int smA = A_FLOATS * (int)sizeof(float);
    int smB = B_FLOATS * (int)sizeof(float);
    cudaFuncSetAttribute(qkv_kernel,  cudaFuncAttributeMaxDynamicSharedMemorySize, smA);
    cudaFuncSetAttribute(attn_kernel, cudaFuncAttributeMaxDynamicSharedMemorySize, smB);

    int blocksA = (n + 63) / 64;
    qkv_kernel<<<blocksA, 192, smA>>>(feat, Wq, bq, gq, betaq,
                                      Wk, bk, gk, betak, Wv, bv, Ww1, gw, n);

    int occ = 0;
    cudaOccupancyMaxActiveBlocksPerMultiprocessor(&occ, attn_kernel, 384, smB);
    if (occ < 1) occ = 1;
    int nsm = 0;
    cudaDeviceGetAttribute(&nsm, cudaDevAttrMultiProcessorCount, 0);
    if (nsm <= 0) nsm = 148;
    int blocksB = occ * nsm;
    int quads = (n + 3) / 4;
    if (blocksB > quads) blocksB = quads;

    attn_kernel<<<blocksB, 384, smB>>>(coord, ref,
                                       Wp1, bp1, gp, betap, Wp2, bp2,
                                       Ww1, bw1, gw, betaw, Ww2, bw2,
                                       (float*)d_out, n);
}

// round 4
// speedup vs baseline: 2.2353x; 1.0017x over previous
#include <cuda_runtime.h>

#define NMAX 50000
#define C 96

__device__ float g_v[NMAX * C];
__device__ float g_Q1[NMAX * 8];
__device__ float g_K1[NMAX * 8];

// ---------------------------------------------------------------------------
// Kernel A: v = feat@Wv+bv, Q1 = relu(bn(feat@Wq+bq))@Ww1f, K1 likewise.
// 64 rows/block, 192 threads, 8x4 register tile, all-float4 smem loads.
// ---------------------------------------------------------------------------
#define A_FEATT 0            // 96*68
#define A_WS    6528         // 96*96
#define A_W1F   15744        // 576
#define A_ROWS  16320        // 64*100
#define A_FLOATS 22720

__global__ __launch_bounds__(192) void qkv_kernel(
    const float* __restrict__ feat,
    const float* __restrict__ Wq, const float* __restrict__ bq,
    const float* __restrict__ gq, const float* __restrict__ betaq,
    const float* __restrict__ Wk, const float* __restrict__ bk,
    const float* __restrict__ gk, const float* __restrict__ betak,
    const float* __restrict__ Wv, const float* __restrict__ bv,
    const float* __restrict__ Ww1, const float* __restrict__ gw,
    int n)
{
    extern __shared__ float sm[];
    float* featT = sm + A_FEATT;   // [96][68]
    float* Ws    = sm + A_WS;      // [96][96]
    float* Ww1fs = sm + A_W1F;     // [96][6]
    float* rows  = sm + A_ROWS;    // [64][100]
    const int tid = threadIdx.x;
    const int tx = tid % 24, ty = tid / 24;   // 24 col-groups x 8 row-groups
    const int base = blockIdx.x * 64;

    for (int i = tid; i < 64 * 96; i += 192) {
        int r = i / 96, j = i % 96;
        featT[j * 68 + r] = (base + r < n) ? feat[(base + r) * 96 + j] : 0.f;
    }
    for (int i = tid; i < 576; i += 192) {
        int g = i % 6;
        Ww1fs[i] = Ww1[i] * (gw[g] * rsqrtf(1.00001f));
    }

    for (int m = 0; m < 3; m++) {
        const float* W = (m == 0) ? Wq : ((m == 1) ? Wk : Wv);
        __syncthreads();
        for (int i = tid; i < 96 * 96; i += 192) Ws[i] = W[i];
        __syncthreads();

        float acc[8][4];
        #pragma unroll
        for (int a = 0; a < 8; a++)
            #pragma unroll
            for (int b = 0; b < 4; b++) acc[a][b] = 0.f;

        #pragma unroll 4
        for (int j = 0; j < 96; j++) {
            float4 f0 = *(const float4*)&featT[j * 68 + 8 * ty];
            float4 f1 = *(const float4*)&featT[j * 68 + 8 * ty + 4];
            float4 w4 = *(const float4*)&Ws[j * 96 + 4 * tx];
            float fr[8] = {f0.x, f0.y, f0.z, f0.w, f1.x, f1.y, f1.z, f1.w};
            float wv[4] = {w4.x, w4.y, w4.z, w4.w};
            #pragma unroll
            for (int a = 0; a < 8; a++)
                #pragma unroll
                for (int b = 0; b < 4; b++)
                    acc[a][b] += fr[a] * wv[b];
        }

        if (m == 2) {
            int c = 4 * tx;
            float4 bb = *(const float4*)&bv[c];
            #pragma unroll
            for (int a = 0; a < 8; a++) {
                int row = base + 8 * ty + a;
                if (row < n) {
                    float4 o = {acc[a][0] + bb.x, acc[a][1] + bb.y,
                                acc[a][2] + bb.z, acc[a][3] + bb.w};
                    *(float4*)&g_v[row * 96 + c] = o;
                }
            }
        } else {
            int c = 4 * tx;
            const float* bsrc = (m == 0) ? bq : bk;
            const float* gsrc = (m == 0) ? gq : gk;
            const float* besrc = (m == 0) ? betaq : betak;
            float4 bb = *(const float4*)&bsrc[c];
            float4 gg = *(const float4*)&gsrc[c];
            float4 be = *(const float4*)&besrc[c];
            float rs = rsqrtf(1.00001f);
            float aa[4] = {gg.x * rs, gg.y * rs, gg.z * rs, gg.w * rs};
            float bba[4] = {bb.x, bb.y, bb.z, bb.w};
            float bea[4] = {be.x, be.y, be.z, be.w};
            #pragma unroll
            for (int a = 0; a < 8; a++) {
                float4 o;
                o.x = fmaxf((acc[a][0] + bba[0]) * aa[0] + bea[0], 0.f);
                o.y = fmaxf((acc[a][1] + bba[1]) * aa[1] + bea[1], 0.f);
                o.z = fmaxf((acc[a][2] + bba[2]) * aa[2] + bea[2], 0.f);
                o.w = fmaxf((acc[a][3] + bba[3]) * aa[3] + bea[3], 0.f);
                *(float4*)&rows[(8 * ty + a) * 100 + c] = o;
            }
            __syncthreads();
            float* dst = (m == 0) ? g_Q1 : g_K1;
            for (int i = tid; i < 384; i += 192) {
                int r = i / 6, g = i % 6;
                if (base + r < n) {
                    float s = 0.f;
                    #pragma unroll 8
                    for (int c2 = 0; c2 < 96; c2++)
                        s += rows[r * 100 + c2] * Ww1fs[c2 * 6 + g];
                    dst[(base + r) * 8 + g] = s;
                }
            }
        }
    }
}

// ---------------------------------------------------------------------------
// Kernel B: fused attention. 384 threads = 4 point-lanes x 96.
// ---------------------------------------------------------------------------
// shared smem offsets (floats)
#define SH_WP2T 0        // [96][100]
#define SH_FT   9600     // [6][100]
#define SH_WP1F 10200    // [96][4]
#define SH_BP2  10584    // 96
#define SH_WW2  10680    // 40
#define SH_BW2  10720    // 8
#define SH_CB   10728    // 8
#define SH_W1F  10736    // 576
#define SH_PART 11312    // [16][96]
#define SH_LANE 12848
// per-lane (floats)
#define L_HT   0         // [16][100] h; aliased as At[6][100] later
#define L_WH   1600      // [16][8]
#define L_LW   1728      // [16][8]
#define L_POS  1856      // [16][4]
#define L_MSK  1920      // 16
#define L_SW   1936      // 8
#define L_IDX  1944      // 2 parities x 16 ints
#define LZ     1984
#define B_FLOATS (SH_LANE + 4 * LZ)

__global__ __launch_bounds__(384, 2) void attn_kernel(
    const float* __restrict__ coord, const int* __restrict__ refidx,
    const float* __restrict__ Wp1, const float* __restrict__ bp1,
    const float* __restrict__ gp,  const float* __restrict__ betap,
    const float* __restrict__ Wp2, const float* __restrict__ bp2,
    const float* __restrict__ Ww1, const float* __restrict__ bw1,
    const float* __restrict__ gw,  const float* __restrict__ betaw,
    const float* __restrict__ Ww2, const float* __restrict__ bw2,
    float* __restrict__ out, int n)
{
    extern __shared__ float sm[];
    float* Wp2T  = sm + SH_WP2T;
    float* Fts   = sm + SH_FT;
    float* Wp1f  = sm + SH_WP1F;
    float* bp2s  = sm + SH_BP2;
    float* Ww2s  = sm + SH_WW2;
    float* bw2s  = sm + SH_BW2;
    float* CBs   = sm + SH_CB;
    float* Ww1fs = sm + SH_W1F;
    float* part  = sm + SH_PART;

    const int tid = threadIdx.x;
    const int pp  = tid / 96;      // lane (point slot) 0..3
    const int jr  = tid % 96;      // j / c role
    const int sL  = jr & 15, gL = jr >> 4;   // (s,g) role, 16-lane shfl groups

    float* lane  = sm + SH_LANE + pp * LZ;
    float* hT    = lane + L_HT;
    float* At    = lane + L_HT;    // alias
    float* whes  = lane + L_WH;
    float* l2w   = lane + L_LW;
    float* poss  = lane + L_POS;
    float* masks = lane + L_MSK;
    float* swv   = lane + L_SW;
    int*   idxp  = (int*)(lane + L_IDX);

    // ---- one-time staging ----
    for (int i = tid; i < 9216; i += 384)
        Wp2T[(i % 96) * 100 + i / 96] = Wp2[i];
    if (tid < 96) {
        float ap = gp[tid] * rsqrtf(1.00001f);
        Wp1f[tid * 4 + 0] = Wp1[tid]       * ap;
        Wp1f[tid * 4 + 1] = Wp1[96 + tid]  * ap;
        Wp1f[tid * 4 + 2] = Wp1[192 + tid] * ap;
        Wp1f[tid * 4 + 3] = bp1[tid] * ap + betap[tid];
        bp2s[tid] = bp2[tid];
    }
    if (tid < 36) Ww2s[tid] = Ww2[tid];
    if (tid < 6)  bw2s[tid] = bw2[tid];
    for (int i = tid; i < 576; i += 384) {
        int g = i % 6;
        Ww1fs[i] = Ww1[i] * (gw[g] * rsqrtf(1.00001f));
    }
    __syncthreads();
    for (int i = tid; i < 576; i += 384) {
        int j = i / 6, g = i % 6;
        float f = 0.f;
        #pragma unroll 8
        for (int c = 0; c < 96; c++) f += Wp2T[c * 100 + j] * Ww1fs[c * 6 + g];
        Fts[g * 100 + j] = f;
    }
    if (tid < 6) {
        float aw = gw[tid] * rsqrtf(1.00001f);
        float cb = bw1[tid] * aw + betaw[tid];
        for (int c = 0; c < 96; c++) cb += bp2s[c] * Ww1fs[c * 6 + tid];
        CBs[tid] = cb;
    }
    __syncthreads();

    int par = 0;
    for (int it = blockIdx.x; it * 4 < n; it += gridDim.x) {
        int nn = it * 4 + pp;
        bool act = (nn < n);

        // ---- ph1: idx / mask / relative positions ----
        if (act && jr < 16) {
            int raw = refidx[nn * 16 + jr];
            int vv = raw + 1;
            masks[jr] = (vv > 0) ? 1.f : ((vv < 0) ? -1.f : 0.f);
            int idx = (raw < 0) ? raw + n : raw;
            idxp[par * 16 + jr] = idx;
            float cx = coord[nn * 3 + 0], cy = coord[nn * 3 + 1], cz = coord[nn * 3 + 2];
            poss[jr * 4 + 0] = coord[idx * 3 + 0] - cx;
            poss[jr * 4 + 1] = coord[idx * 3 + 1] - cy;
            poss[jr * 4 + 2] = coord[idx * 3 + 2] - cz;
        }
        __syncthreads();

        // ---- ph2: h[s] per thread-j ----
        float h[16];
        if (act) {
            float4 wp = *(const float4*)&Wp1f[jr * 4];
            #pragma unroll
            for (int s = 0; s < 16; s++) {
                float4 p = *(const float4*)&poss[s * 4];
                float hv = fmaxf(wp.w + p.x * wp.x + p.y * wp.y + p.z * wp.z, 0.f);
                h[s] = hv;
                hT[s * 100 + jr] = hv;
            }
        }
        __syncthreads();

        // ---- ph3: wh[s,g] = relu(l1) ----
        if (act) {
            int idx = idxp[par * 16 + sL];
            float acc = CBs[gL] + g_K1[idx * 8 + gL] - g_Q1[nn * 8 + gL];
            #pragma unroll
            for (int j = 0; j < 96; j += 4) {
                float4 hh = *(const float4*)&hT[sL * 100 + j];
                float4 ff = *(const float4*)&Fts[gL * 100 + j];
                acc += hh.x * ff.x + hh.y * ff.y + hh.z * ff.z + hh.w * ff.w;
            }
            whes[sL * 8 + gL] = fmaxf(acc, 0.f);
        }
        __syncthreads();

        // ---- ph456: l2, softmax over s via 16-lane shfl, masked weights ----
        if (act) {
            float l2 = bw2s[gL];
            #pragma unroll
            for (int gg = 0; gg < 6; gg++)
                l2 += whes[sL * 8 + gg] * Ww2s[gg * 6 + gL];
            float mx = l2;
            #pragma unroll
            for (int off = 8; off >= 1; off >>= 1)
                mx = fmaxf(mx, __shfl_xor_sync(0xffffffffu, mx, off, 16));
            float e  = __expf(l2 - mx);
            float em = e * masks[sL];
            float ss = e, ms = em;
            #pragma unroll
            for (int off = 8; off >= 1; off >>= 1) {
                ss += __shfl_xor_sync(0xffffffffu, ss, off, 16);
                ms += __shfl_xor_sync(0xffffffffu, ms, off, 16);
            }
            l2w[sL * 8 + gL] = em / ss;
            if (sL == 0) swv[gL] = ms / ss;
        }
        __syncthreads();

        // ---- ph7: A[j,g] = sum_s h[s,j] w[s,g] (thread-j role) ----
        if (act) {
            float A0 = 0.f, A1 = 0.f, A2 = 0.f, A3 = 0.f, A4 = 0.f, A5 = 0.f;
            #pragma unroll
            for (int s = 0; s < 16; s++) {
                float hv = h[s];
                float4 wa = *(const float4*)&l2w[s * 8];
                float4 wb = *(const float4*)&l2w[s * 8 + 4];
                A0 += hv * wa.x; A1 += hv * wa.y; A2 += hv * wa.z;
                A3 += hv * wa.w; A4 += hv * wb.x; A5 += hv * wb.y;
            }
            At[0 * 100 + jr] = A0; At[1 * 100 + jr] = A1; At[2 * 100 + jr] = A2;
            At[3 * 100 + jr] = A3; At[4 * 100 + jr] = A4; At[5 * 100 + jr] = A5;
        }
        __syncthreads();

        // ---- ph8a: cooperative Wp2^T @ A — each thread handles a j-quarter
        //      for ALL 4 points (reads Wp2 column once per 4 points) ----
        {
            int c = jr, qq = pp, g = jr >> 4;
            int j0 = qq * 24;
            float pt[4] = {0.f, 0.f, 0.f, 0.f};
            #pragma unroll
            for (int j = 0; j < 24; j += 4) {
                float4 wv = *(const float4*)&Wp2T[c * 100 + j0 + j];
                #pragma unroll
                for (int p = 0; p < 4; p++) {
                    const float* Ap = sm + SH_LANE + p * LZ + L_HT;
                    float4 av = *(const float4*)&Ap[g * 100 + j0 + j];
                    pt[p] += wv.x * av.x + wv.y * av.y + wv.z * av.z + wv.w * av.w;
                }
            }
            #pragma unroll
            for (int p = 0; p < 4; p++)
                part[(qq * 4 + p) * 96 + c] = pt[p];
        }
        __syncthreads();

        // ---- ph8b: combine quarters + v-gather term, store out ----
        if (act) {
            int c = jr, g = jr >> 4;
            const int* idq = (const int*)(lane + L_IDX) + par * 16;
            float o = bp2s[c] * swv[g];
            o += part[(0 * 4 + pp) * 96 + c] + part[(1 * 4 + pp) * 96 + c]
               + part[(2 * 4 + pp) * 96 + c] + part[(3 * 4 + pp) * 96 + c];
            float vv[16];
            #pragma unroll
            for (int s = 0; s < 16; s++)
                vv[s] = g_v[idq[s] * 96 + c];
            #pragma unroll
            for (int s = 0; s < 16; s++)
                o += vv[s] * l2w[s * 8 + g];
            out[nn * 96 + c] = o;
        }
        par ^= 1;
    }
}

extern "C" void kernel_launch(void* const* d_in, const int* in_sizes, int n_in,
                              void* d_out, int out_size) {
    const float* feat  = (const float*)d_in[0];
    const float* coord = (const float*)d_in[1];
    const int*   ref   = (const int*)d_in[2];
    const float* Wq    = (const float*)d_in[3];
    const float* bq    = (const float*)d_in[4];
    const float* gq    = (const float*)d_in[5];
    const float* betaq = (const float*)d_in[6];
    const float* Wk    = (const float*)d_in[7];
    const float* bk    = (const float*)d_in[8];
    const float* gk    = (const float*)d_in[9];
    const float* betak = (const float*)d_in[10];
    const float* Wv    = (const float*)d_in[11];
    const float* bv    = (const float*)d_in[12];
    const float* Wp1   = (const float*)d_in[13];
    const float* bp1   = (const float*)d_in[14];
    const float* gp    = (const float*)d_in[15];
    const float* betap = (const float*)d_in[16];
    const float* Wp2   = (const float*)d_in[17];
    const float* bp2   = (const float*)d_in[18];
    const float* Ww1   = (const float*)d_in[19];
    const float* bw1   = (const float*)d_in[20];
    const float* gw    = (const float*)d_in[21];
    const float* betaw = (const float*)d_in[22];
    const float* Ww2   = (const float*)d_in[23];
    const float* bw2   = (const float*)d_in[24];

    int n = in_sizes[1] / 3;

    int smA = A_FLOATS * (int)sizeof(float);
    int smB = B_FLOATS * (int)sizeof(float);
    cudaFuncSetAttribute(qkv_kernel,  cudaFuncAttributeMaxDynamicSharedMemorySize, smA);
    cudaFuncSetAttribute(attn_kernel, cudaFuncAttributeMaxDynamicSharedMemorySize, smB);

    int blocksA = (n + 63) / 64;
    qkv_kernel<<<blocksA, 192, smA>>>(feat, Wq, bq, gq, betaq,
                                      Wk, bk, gk, betak, Wv, bv, Ww1, gw, n);

    int occ = 0;
    cudaOccupancyMaxActiveBlocksPerMultiprocessor(&occ, attn_kernel, 384, smB);
    if (occ < 1) occ = 1;
    int nsm = 0;
    cudaDeviceGetAttribute(&nsm, cudaDevAttrMultiProcessorCount, 0);
    if (nsm <= 0) nsm = 148;
    int blocksB = occ * nsm;
    int quads = (n + 3) / 4;
    if (blocksB > quads) blocksB = quads;

    attn_kernel<<<blocksB, 384, smB>>>(coord, ref,
                                       Wp1, bp1, gp, betap, Wp2, bp2,
                                       Ww1, bw1, gw, betaw, Ww2, bw2,
                                       (float*)d_out, n);
}